// round 11
// baseline (speedup 1.0000x reference)
#include <cuda_runtime.h>
#include <cstdint>

#define SCALE 0.17677669529663687f     // 32^-0.5
typedef unsigned long long ull;

// Packed dual-fp32 FMA (sm_100+): acc(2xf32) += a(2xf32) * b(2xf32)
#define FMA2(acc, a, b) \
    asm("fma.rn.f32x2 %0, %1, %2, %0;" : "+l"(acc) : "l"(a), "l"(b))
// Duplicate a scalar float into both lanes of a 64-bit pack
#define PACK2(u, f) \
    asm("mov.b64 %0, {%1, %2};" : "=l"(u) : "f"(f), "f"(f))

#define CP_ASYNC16(dst_u32, src_ptr) \
    asm volatile("cp.async.ca.shared.global [%0], [%1], 16;" \
                 :: "r"(dst_u32), "l"(src_ptr))
#define CP_COMMIT() asm volatile("cp.async.commit_group;")
#define CP_WAIT0()  asm volatile("cp.async.wait_group 0;" ::: "memory")

// smem layout (float offsets)
#define OFF_KT 0          // Kt[32][512]   d-major K
#define OFF_VT 16384      // Vt[32][512]   c-major V, k-pair swizzled by ch-grp
#define OFF_PD 32768      // Pd[32][516] ALIASED by Red[16][32][36] (18432 f)
#define OFF_QR 51200      // Qr[32][36]  raw Q staging (cp.async)
#define OFF_SR 52352      // Sr[2][32]   softmax partial sums
#define OFF_W  52416      // conv w [32*9]
#define OFF_B  52704      // conv b [32]
#define SMEM_FLOATS 52736 // 210944 bytes

// ---------------------------------------------------------------------------
// 307us champion (R6) + ONE change: epilogue LePE conv remapped to
// (warp = channel quad, lane = token row) -> V tap loads go from 8-way bank
// conflict to ~conflict-free (fixed c per warp; ko spreads banks over rows).
// One CTA per (window, head). 512 threads, 16 warps, 16 passes of 32 q-rows.
// ---------------------------------------------------------------------------
__global__ __launch_bounds__(512, 1)
void fused_attn_kernel(const float* __restrict__ qkv,
                       const float* __restrict__ cw,
                       const float* __restrict__ cb,
                       float* __restrict__ attn_out,
                       float* __restrict__ xout) {
    extern __shared__ float sm[];
    float* Kt  = sm + OFF_KT;
    float* Vt  = sm + OFF_VT;
    float* Pd  = sm + OFF_PD;
    float* Red = sm + OFF_PD;      // alias (Pd dead when Red live)
    float* Qr  = sm + OFF_QR;
    float* Sr  = sm + OFF_SR;
    float* Wsh = sm + OFF_W;
    float* Bsh = sm + OFF_B;

    int wh = blockIdx.x;  int n = wh >> 3, h = wh & 7;
    int b  = n >> 3,      w2 = n & 7;
    int tid = threadIdx.x, lane = tid & 31, warp = tid >> 5;
    int wg = warp & 7, half = warp >> 3;
    int colb = half * 256;                     // S-phase column half

    const float* Qg = qkv + (size_t)(0 + b) * 4096 * 256;
    const float* Kg = qkv + (size_t)(4 + b) * 4096 * 256;
    const float* Vg = qkv + (size_t)(8 + b) * 4096 * 256;

    uint32_t qr_base = (uint32_t)__cvta_generic_to_shared(Qr);
    int qrow = (tid & 255) >> 3, qcq = tid & 7;

    // ---- prologue: prefetch Q(pass 0); fill Kt, Vt, conv params ----
    if (tid < 256) {
        int l = (qrow >> 3) * 64 + w2 * 8 + (qrow & 7);
        CP_ASYNC16(qr_base + (uint32_t)(qrow * 36 + qcq * 4) * 4,
                   Qg + (size_t)l * 256 + h * 32 + qcq * 4);
    }
    CP_COMMIT();
    {   // Kt: one column per thread
        int c = tid;
        int l = (c >> 3) * 64 + w2 * 8 + (c & 7);
        const float4* src = (const float4*)(Kg + (size_t)l * 256 + h * 32);
        #pragma unroll
        for (int v4 = 0; v4 < 8; v4++) {
            float4 v = src[v4];
            Kt[(4 * v4 + 0) * 512 + c] = v.x;
            Kt[(4 * v4 + 1) * 512 + c] = v.y;
            Kt[(4 * v4 + 2) * 512 + c] = v.z;
            Kt[(4 * v4 + 3) * 512 + c] = v.w;
        }
    }
    {   // Vt transposed + k-pair swizzle (slot = (k>>1) ^ 4*((c>>3)&3))
        int c  = tid & 31;
        int sw = 4 * ((c >> 3) & 3);
        for (int k = tid >> 5; k < 512; k += 16) {
            int l = (k >> 3) * 64 + w2 * 8 + (k & 7);
            Vt[c * 512 + 2 * ((k >> 1) ^ sw) + (k & 1)] =
                Vg[(size_t)l * 256 + h * 32 + c];
        }
    }
    for (int i = tid; i < 288; i += 512) Wsh[i] = cw[(h * 32) * 9 + i];
    if (tid < 32) Bsh[tid] = cb[h * 32 + tid];
    CP_WAIT0();
    __syncthreads();

    float* outp = attn_out + (size_t)wh * 512 * 512;
    const float* Ktb = Kt + colb + 4 * lane;

    // PV mapping: lane = (rs, cq): rows {rs + 8j}, channels {8cq .. 8cq+7}
    int rs = lane >> 2, cq = lane & 3;
    int vsw = cq << 2;

    for (int pass = 0; pass < 16; pass++) {
        // ============ S phase: warp = 4 rows x 256 cols ============
        ull sacc[4][4];
        #pragma unroll
        for (int r = 0; r < 4; r++)
            #pragma unroll
            for (int j = 0; j < 4; j++) sacc[r][j] = 0ull;

        const float* Qb = Qr + (wg * 4) * 36;
        #pragma unroll 4
        for (int d = 0; d < 32; d += 2) {
            float2 qf0 = *(const float2*)(Qb + 0 * 36 + d);
            float2 qf1 = *(const float2*)(Qb + 1 * 36 + d);
            float2 qf2 = *(const float2*)(Qb + 2 * 36 + d);
            float2 qf3 = *(const float2*)(Qb + 3 * 36 + d);
            ull q0x, q0y, q1x, q1y, q2x, q2y, q3x, q3y;
            PACK2(q0x, qf0.x); PACK2(q0y, qf0.y);
            PACK2(q1x, qf1.x); PACK2(q1y, qf1.y);
            PACK2(q2x, qf2.x); PACK2(q2y, qf2.y);
            PACK2(q3x, qf3.x); PACK2(q3y, qf3.y);
            #pragma unroll
            for (int p = 0; p < 2; p++) {
                ulonglong2 kv0 = *(const ulonglong2*)(Ktb + d * 512 + 128 * p);
                ulonglong2 kv1 = *(const ulonglong2*)(Ktb + (d + 1) * 512 + 128 * p);
                FMA2(sacc[0][2 * p],     kv0.x, q0x);
                FMA2(sacc[0][2 * p + 1], kv0.y, q0x);
                FMA2(sacc[1][2 * p],     kv0.x, q1x);
                FMA2(sacc[1][2 * p + 1], kv0.y, q1x);
                FMA2(sacc[2][2 * p],     kv0.x, q2x);
                FMA2(sacc[2][2 * p + 1], kv0.y, q2x);
                FMA2(sacc[3][2 * p],     kv0.x, q3x);
                FMA2(sacc[3][2 * p + 1], kv0.y, q3x);
                FMA2(sacc[0][2 * p],     kv1.x, q0y);
                FMA2(sacc[0][2 * p + 1], kv1.y, q0y);
                FMA2(sacc[1][2 * p],     kv1.x, q1y);
                FMA2(sacc[1][2 * p + 1], kv1.y, q1y);
                FMA2(sacc[2][2 * p],     kv1.x, q2y);
                FMA2(sacc[2][2 * p + 1], kv1.y, q2y);
                FMA2(sacc[3][2 * p],     kv1.x, q3y);
                FMA2(sacc[3][2 * p + 1], kv1.y, q3y);
            }
        }

        // ========== softmax (no max-subtract) + attn STG + P STS ==========
        float v[4][8];
        #pragma unroll
        for (int rr = 0; rr < 4; rr++) {
            float s = 0.f;
            #pragma unroll
            for (int u = 0; u < 4; u++) {
                float2 f = *(float2*)&sacc[rr][u];
                float e0 = __expf(f.x * SCALE);
                float e1 = __expf(f.y * SCALE);
                v[rr][2 * u] = e0; v[rr][2 * u + 1] = e1;
                s += e0 + e1;
            }
            #pragma unroll
            for (int off = 16; off; off >>= 1)
                s += __shfl_xor_sync(0xffffffffu, s, off);
            if (lane == 0) Sr[half * 32 + wg * 4 + rr] = s;
        }
        __syncthreads();                       // (1) Sr ready
        #pragma unroll
        for (int rr = 0; rr < 4; rr++) {
            int row = wg * 4 + rr;
            float inv = 1.0f / (Sr[row] + Sr[32 + row]);
            float* orow = outp + (size_t)(pass * 32 + row) * 512 + colb + 4 * lane;
            float* prow = Pd + row * 516 + colb + 4 * lane;
            #pragma unroll
            for (int p = 0; p < 2; p++) {
                float4 o = make_float4(v[rr][4 * p] * inv, v[rr][4 * p + 1] * inv,
                                       v[rr][4 * p + 2] * inv, v[rr][4 * p + 3] * inv);
                *(float4*)(orow + 128 * p) = o;
                *(float4*)(prow + 128 * p) = o;
            }
        }
        __syncthreads();                       // (2) Pd ready

        // prefetch Q for next pass (overlaps PV)
        if (pass < 15 && tid < 256) {
            int grow = (pass + 1) * 32 + qrow;
            int l = (grow >> 3) * 64 + w2 * 8 + (grow & 7);
            CP_ASYNC16(qr_base + (uint32_t)(qrow * 36 + qcq * 4) * 4,
                       Qg + (size_t)l * 256 + h * 32 + qcq * 4);
        }
        CP_COMMIT();

        // ================= PV phase (warp k-range: 16 k-pairs) ============
        ull pacc[4][8];
        #pragma unroll
        for (int j = 0; j < 4; j++)
            #pragma unroll
            for (int i = 0; i < 8; i++) pacc[j][i] = 0ull;
        {
            const float* Pk = Pd + rs * 516 + 32 * warp;
            const float* Vk = Vt + (8 * cq) * 512 + 32 * warp;
            #pragma unroll 4
            for (int a = 0; a < 16; a++) {
                ull p0 = *(const ull*)(Pk + 0 * 4128 + 2 * a);   // 8*516
                ull p1 = *(const ull*)(Pk + 1 * 4128 + 2 * a);
                ull p2 = *(const ull*)(Pk + 2 * 4128 + 2 * a);
                ull p3 = *(const ull*)(Pk + 3 * 4128 + 2 * a);
                int voff = 2 * (a ^ vsw);
                #pragma unroll
                for (int i = 0; i < 8; i++) {
                    ull vv = *(const ull*)(Vk + i * 512 + voff);
                    FMA2(pacc[0][i], p0, vv);
                    FMA2(pacc[1][i], p1, vv);
                    FMA2(pacc[2][i], p2, vv);
                    FMA2(pacc[3][i], p3, vv);
                }
            }
        }
        __syncthreads();                       // (3) PV done, Pd dead

        // ---- per-warp partials into Red[16][32][36] (aliases Pd) ----
        {
            float* rw = Red + warp * 32 * 36;
            #pragma unroll
            for (int j = 0; j < 4; j++) {
                int row = rs + 8 * j;
                float4 a4, b4;
                float2 f;
                f = *(float2*)&pacc[j][0]; a4.x = f.x + f.y;
                f = *(float2*)&pacc[j][1]; a4.y = f.x + f.y;
                f = *(float2*)&pacc[j][2]; a4.z = f.x + f.y;
                f = *(float2*)&pacc[j][3]; a4.w = f.x + f.y;
                f = *(float2*)&pacc[j][4]; b4.x = f.x + f.y;
                f = *(float2*)&pacc[j][5]; b4.y = f.x + f.y;
                f = *(float2*)&pacc[j][6]; b4.z = f.x + f.y;
                f = *(float2*)&pacc[j][7]; b4.w = f.x + f.y;
                *(float4*)(rw + row * 36 + 8 * cq)     = a4;
                *(float4*)(rw + row * 36 + 8 * cq + 4) = b4;
            }
        }
        __syncthreads();                       // (4) Red ready

        // ---- reduce 16 partials + fused LePE + STG x (threads 0..255) ----
        // NEW MAPPING: warp = channel quad (fixed c per warp), lane = row.
        // V tap loads: fixed c -> ko(r) spreads banks -> no 8-way conflict.
        if (tid < 256) {
            int r  = tid & 31;                 // token row within pass (lane)
            int c0 = (tid >> 5) * 4;           // channel quad (warp)
            float4 o = make_float4(0.f, 0.f, 0.f, 0.f);
            #pragma unroll
            for (int w = 0; w < 16; w++) {
                float4 t4 = *(const float4*)(Red + (w * 32 + r) * 36 + c0);
                o.x += t4.x; o.y += t4.y; o.z += t4.z; o.w += t4.w;
            }
            int t  = pass * 32 + r;            // window token
            int hs = t >> 3, ws = t & 7;
            float ov[4] = {o.x + Bsh[c0], o.y + Bsh[c0 + 1],
                           o.z + Bsh[c0 + 2], o.w + Bsh[c0 + 3]};
            int swc = 4 * ((c0 >> 3) & 3);
            #pragma unroll
            for (int dy = -1; dy <= 1; dy++) {
                if ((unsigned)(hs + dy) >= 64u) continue;
                #pragma unroll
                for (int dx = -1; dx <= 1; dx++) {
                    if ((unsigned)(ws + dx) >= 8u) continue;
                    int kk = t + dy * 8 + dx;
                    int ko = 2 * ((kk >> 1) ^ swc) + (kk & 1);
                    int wi = (dy + 1) * 3 + (dx + 1);
                    #pragma unroll
                    for (int cc = 0; cc < 4; cc++)
                        ov[cc] += Vt[(c0 + cc) * 512 + ko] * Wsh[(c0 + cc) * 9 + wi];
                }
            }
            int l = hs * 64 + w2 * 8 + ws;
            *(float4*)(xout + ((size_t)b * 4096 + l) * 256 + h * 32 + c0) =
                make_float4(ov[0], ov[1], ov[2], ov[3]);
        }

        CP_WAIT0();                            // Qr(pass+1) landed
        __syncthreads();                       // (5) epilogue done; Qr visible
    }
}

// ---------------------------------------------------------------------------
extern "C" void kernel_launch(void* const* d_in, const int* in_sizes, int n_in,
                              void* d_out, int out_size) {
    const float* qkv = (const float*)d_in[0];
    const float* cw  = (const float*)d_in[1];
    const float* cb  = (const float*)d_in[2];
    float* xout = (float*)d_out;
    float* attn = xout + (size_t)4 * 4096 * 256;    // x first, then attn

    const int SMEM = SMEM_FLOATS * 4;               // 210944 B
    cudaFuncSetAttribute(fused_attn_kernel,
                         cudaFuncAttributeMaxDynamicSharedMemorySize, SMEM);

    fused_attn_kernel<<<256, 512, SMEM>>>(qkv, cw, cb, attn, xout);
}

// round 12
// speedup vs baseline: 1.0040x; 1.0040x over previous
#include <cuda_runtime.h>
#include <cstdint>

#define SCALE 0.17677669529663687f     // 32^-0.5
typedef unsigned long long ull;

// Packed dual-fp32 FMA (sm_100+): acc(2xf32) += a(2xf32) * b(2xf32)
#define FMA2(acc, a, b) \
    asm("fma.rn.f32x2 %0, %1, %2, %0;" : "+l"(acc) : "l"(a), "l"(b))
// Duplicate a scalar float into both lanes of a 64-bit pack
#define PACK2(u, f) \
    asm("mov.b64 %0, {%1, %2};" : "=l"(u) : "f"(f), "f"(f))

#define CP_ASYNC16(dst_u32, src_ptr) \
    asm volatile("cp.async.ca.shared.global [%0], [%1], 16;" \
                 :: "r"(dst_u32), "l"(src_ptr))
#define CP_COMMIT() asm volatile("cp.async.commit_group;")
#define CP_WAIT0()  asm volatile("cp.async.wait_group 0;" ::: "memory")

// smem layout (float offsets)
#define OFF_KT 0          // Kt[32][512]   d-major K
#define OFF_VT 16384      // Vt[32][512]   c-major V, k-pair swizzled by ch-grp
#define OFF_PD 32768      // Pd[32][516] ALIASED by Red[16][32][36] (18432 f)
#define OFF_QR 51200      // Qr[32][36]  raw Q staging (cp.async)
#define OFF_SR 52352      // Sr[2][32]   softmax partial sums
#define OFF_W  52416      // conv w [32*9]
#define OFF_B  52704      // conv b [32]
#define SMEM_FLOATS 52736 // 210944 bytes

// ---------------------------------------------------------------------------
// 307us champion (R6) + ONE change: epilogue LePE conv remapped to
// (warp = channel quad, lane = token row) -> V tap loads go from 8-way bank
// conflict to ~conflict-free (fixed c per warp; ko spreads banks over rows).
// One CTA per (window, head). 512 threads, 16 warps, 16 passes of 32 q-rows.
// ---------------------------------------------------------------------------
__global__ __launch_bounds__(512, 1)
void fused_attn_kernel(const float* __restrict__ qkv,
                       const float* __restrict__ cw,
                       const float* __restrict__ cb,
                       float* __restrict__ attn_out,
                       float* __restrict__ xout) {
    extern __shared__ float sm[];
    float* Kt  = sm + OFF_KT;
    float* Vt  = sm + OFF_VT;
    float* Pd  = sm + OFF_PD;
    float* Red = sm + OFF_PD;      // alias (Pd dead when Red live)
    float* Qr  = sm + OFF_QR;
    float* Sr  = sm + OFF_SR;
    float* Wsh = sm + OFF_W;
    float* Bsh = sm + OFF_B;

    int wh = blockIdx.x;  int n = wh >> 3, h = wh & 7;
    int b  = n >> 3,      w2 = n & 7;
    int tid = threadIdx.x, lane = tid & 31, warp = tid >> 5;
    int wg = warp & 7, half = warp >> 3;
    int colb = half * 256;                     // S-phase column half

    const float* Qg = qkv + (size_t)(0 + b) * 4096 * 256;
    const float* Kg = qkv + (size_t)(4 + b) * 4096 * 256;
    const float* Vg = qkv + (size_t)(8 + b) * 4096 * 256;

    uint32_t qr_base = (uint32_t)__cvta_generic_to_shared(Qr);
    int qrow = (tid & 255) >> 3, qcq = tid & 7;

    // ---- prologue: prefetch Q(pass 0); fill Kt, Vt, conv params ----
    if (tid < 256) {
        int l = (qrow >> 3) * 64 + w2 * 8 + (qrow & 7);
        CP_ASYNC16(qr_base + (uint32_t)(qrow * 36 + qcq * 4) * 4,
                   Qg + (size_t)l * 256 + h * 32 + qcq * 4);
    }
    CP_COMMIT();
    {   // Kt: one column per thread
        int c = tid;
        int l = (c >> 3) * 64 + w2 * 8 + (c & 7);
        const float4* src = (const float4*)(Kg + (size_t)l * 256 + h * 32);
        #pragma unroll
        for (int v4 = 0; v4 < 8; v4++) {
            float4 v = src[v4];
            Kt[(4 * v4 + 0) * 512 + c] = v.x;
            Kt[(4 * v4 + 1) * 512 + c] = v.y;
            Kt[(4 * v4 + 2) * 512 + c] = v.z;
            Kt[(4 * v4 + 3) * 512 + c] = v.w;
        }
    }
    {   // Vt transposed + k-pair swizzle (slot = (k>>1) ^ 4*((c>>3)&3))
        int c  = tid & 31;
        int sw = 4 * ((c >> 3) & 3);
        for (int k = tid >> 5; k < 512; k += 16) {
            int l = (k >> 3) * 64 + w2 * 8 + (k & 7);
            Vt[c * 512 + 2 * ((k >> 1) ^ sw) + (k & 1)] =
                Vg[(size_t)l * 256 + h * 32 + c];
        }
    }
    for (int i = tid; i < 288; i += 512) Wsh[i] = cw[(h * 32) * 9 + i];
    if (tid < 32) Bsh[tid] = cb[h * 32 + tid];
    CP_WAIT0();
    __syncthreads();

    float* outp = attn_out + (size_t)wh * 512 * 512;
    const float* Ktb = Kt + colb + 4 * lane;

    // PV mapping: lane = (rs, cq): rows {rs + 8j}, channels {8cq .. 8cq+7}
    int rs = lane >> 2, cq = lane & 3;
    int vsw = cq << 2;

    for (int pass = 0; pass < 16; pass++) {
        // ============ S phase: warp = 4 rows x 256 cols ============
        ull sacc[4][4];
        #pragma unroll
        for (int r = 0; r < 4; r++)
            #pragma unroll
            for (int j = 0; j < 4; j++) sacc[r][j] = 0ull;

        const float* Qb = Qr + (wg * 4) * 36;
        #pragma unroll 4
        for (int d = 0; d < 32; d += 2) {
            float2 qf0 = *(const float2*)(Qb + 0 * 36 + d);
            float2 qf1 = *(const float2*)(Qb + 1 * 36 + d);
            float2 qf2 = *(const float2*)(Qb + 2 * 36 + d);
            float2 qf3 = *(const float2*)(Qb + 3 * 36 + d);
            ull q0x, q0y, q1x, q1y, q2x, q2y, q3x, q3y;
            PACK2(q0x, qf0.x); PACK2(q0y, qf0.y);
            PACK2(q1x, qf1.x); PACK2(q1y, qf1.y);
            PACK2(q2x, qf2.x); PACK2(q2y, qf2.y);
            PACK2(q3x, qf3.x); PACK2(q3y, qf3.y);
            #pragma unroll
            for (int p = 0; p < 2; p++) {
                ulonglong2 kv0 = *(const ulonglong2*)(Ktb + d * 512 + 128 * p);
                ulonglong2 kv1 = *(const ulonglong2*)(Ktb + (d + 1) * 512 + 128 * p);
                FMA2(sacc[0][2 * p],     kv0.x, q0x);
                FMA2(sacc[0][2 * p + 1], kv0.y, q0x);
                FMA2(sacc[1][2 * p],     kv0.x, q1x);
                FMA2(sacc[1][2 * p + 1], kv0.y, q1x);
                FMA2(sacc[2][2 * p],     kv0.x, q2x);
                FMA2(sacc[2][2 * p + 1], kv0.y, q2x);
                FMA2(sacc[3][2 * p],     kv0.x, q3x);
                FMA2(sacc[3][2 * p + 1], kv0.y, q3x);
                FMA2(sacc[0][2 * p],     kv1.x, q0y);
                FMA2(sacc[0][2 * p + 1], kv1.y, q0y);
                FMA2(sacc[1][2 * p],     kv1.x, q1y);
                FMA2(sacc[1][2 * p + 1], kv1.y, q1y);
                FMA2(sacc[2][2 * p],     kv1.x, q2y);
                FMA2(sacc[2][2 * p + 1], kv1.y, q2y);
                FMA2(sacc[3][2 * p],     kv1.x, q3y);
                FMA2(sacc[3][2 * p + 1], kv1.y, q3y);
            }
        }

        // ========== softmax (no max-subtract) + attn STG + P STS ==========
        float v[4][8];
        #pragma unroll
        for (int rr = 0; rr < 4; rr++) {
            float s = 0.f;
            #pragma unroll
            for (int u = 0; u < 4; u++) {
                float2 f = *(float2*)&sacc[rr][u];
                float e0 = __expf(f.x * SCALE);
                float e1 = __expf(f.y * SCALE);
                v[rr][2 * u] = e0; v[rr][2 * u + 1] = e1;
                s += e0 + e1;
            }
            #pragma unroll
            for (int off = 16; off; off >>= 1)
                s += __shfl_xor_sync(0xffffffffu, s, off);
            if (lane == 0) Sr[half * 32 + wg * 4 + rr] = s;
        }
        __syncthreads();                       // (1) Sr ready
        #pragma unroll
        for (int rr = 0; rr < 4; rr++) {
            int row = wg * 4 + rr;
            float inv = 1.0f / (Sr[row] + Sr[32 + row]);
            float* orow = outp + (size_t)(pass * 32 + row) * 512 + colb + 4 * lane;
            float* prow = Pd + row * 516 + colb + 4 * lane;
            #pragma unroll
            for (int p = 0; p < 2; p++) {
                float4 o = make_float4(v[rr][4 * p] * inv, v[rr][4 * p + 1] * inv,
                                       v[rr][4 * p + 2] * inv, v[rr][4 * p + 3] * inv);
                *(float4*)(orow + 128 * p) = o;
                *(float4*)(prow + 128 * p) = o;
            }
        }
        __syncthreads();                       // (2) Pd ready

        // prefetch Q for next pass (overlaps PV)
        if (pass < 15 && tid < 256) {
            int grow = (pass + 1) * 32 + qrow;
            int l = (grow >> 3) * 64 + w2 * 8 + (grow & 7);
            CP_ASYNC16(qr_base + (uint32_t)(qrow * 36 + qcq * 4) * 4,
                       Qg + (size_t)l * 256 + h * 32 + qcq * 4);
        }
        CP_COMMIT();

        // ================= PV phase (warp k-range: 16 k-pairs) ============
        ull pacc[4][8];
        #pragma unroll
        for (int j = 0; j < 4; j++)
            #pragma unroll
            for (int i = 0; i < 8; i++) pacc[j][i] = 0ull;
        {
            const float* Pk = Pd + rs * 516 + 32 * warp;
            const float* Vk = Vt + (8 * cq) * 512 + 32 * warp;
            #pragma unroll 4
            for (int a = 0; a < 16; a++) {
                ull p0 = *(const ull*)(Pk + 0 * 4128 + 2 * a);   // 8*516
                ull p1 = *(const ull*)(Pk + 1 * 4128 + 2 * a);
                ull p2 = *(const ull*)(Pk + 2 * 4128 + 2 * a);
                ull p3 = *(const ull*)(Pk + 3 * 4128 + 2 * a);
                int voff = 2 * (a ^ vsw);
                #pragma unroll
                for (int i = 0; i < 8; i++) {
                    ull vv = *(const ull*)(Vk + i * 512 + voff);
                    FMA2(pacc[0][i], p0, vv);
                    FMA2(pacc[1][i], p1, vv);
                    FMA2(pacc[2][i], p2, vv);
                    FMA2(pacc[3][i], p3, vv);
                }
            }
        }
        __syncthreads();                       // (3) PV done, Pd dead

        // ---- per-warp partials into Red[16][32][36] (aliases Pd) ----
        {
            float* rw = Red + warp * 32 * 36;
            #pragma unroll
            for (int j = 0; j < 4; j++) {
                int row = rs + 8 * j;
                float4 a4, b4;
                float2 f;
                f = *(float2*)&pacc[j][0]; a4.x = f.x + f.y;
                f = *(float2*)&pacc[j][1]; a4.y = f.x + f.y;
                f = *(float2*)&pacc[j][2]; a4.z = f.x + f.y;
                f = *(float2*)&pacc[j][3]; a4.w = f.x + f.y;
                f = *(float2*)&pacc[j][4]; b4.x = f.x + f.y;
                f = *(float2*)&pacc[j][5]; b4.y = f.x + f.y;
                f = *(float2*)&pacc[j][6]; b4.z = f.x + f.y;
                f = *(float2*)&pacc[j][7]; b4.w = f.x + f.y;
                *(float4*)(rw + row * 36 + 8 * cq)     = a4;
                *(float4*)(rw + row * 36 + 8 * cq + 4) = b4;
            }
        }
        __syncthreads();                       // (4) Red ready

        // ---- reduce 16 partials + fused LePE + STG x (threads 0..255) ----
        // NEW MAPPING: warp = channel quad (fixed c per warp), lane = row.
        // V tap loads: fixed c -> ko(r) spreads banks -> no 8-way conflict.
        if (tid < 256) {
            int r  = tid & 31;                 // token row within pass (lane)
            int c0 = (tid >> 5) * 4;           // channel quad (warp)
            float4 o = make_float4(0.f, 0.f, 0.f, 0.f);
            #pragma unroll
            for (int w = 0; w < 16; w++) {
                float4 t4 = *(const float4*)(Red + (w * 32 + r) * 36 + c0);
                o.x += t4.x; o.y += t4.y; o.z += t4.z; o.w += t4.w;
            }
            int t  = pass * 32 + r;            // window token
            int hs = t >> 3, ws = t & 7;
            float ov[4] = {o.x + Bsh[c0], o.y + Bsh[c0 + 1],
                           o.z + Bsh[c0 + 2], o.w + Bsh[c0 + 3]};
            int swc = 4 * ((c0 >> 3) & 3);
            #pragma unroll
            for (int dy = -1; dy <= 1; dy++) {
                if ((unsigned)(hs + dy) >= 64u) continue;
                #pragma unroll
                for (int dx = -1; dx <= 1; dx++) {
                    if ((unsigned)(ws + dx) >= 8u) continue;
                    int kk = t + dy * 8 + dx;
                    int ko = 2 * ((kk >> 1) ^ swc) + (kk & 1);
                    int wi = (dy + 1) * 3 + (dx + 1);
                    #pragma unroll
                    for (int cc = 0; cc < 4; cc++)
                        ov[cc] += Vt[(c0 + cc) * 512 + ko] * Wsh[(c0 + cc) * 9 + wi];
                }
            }
            int l = hs * 64 + w2 * 8 + ws;
            *(float4*)(xout + ((size_t)b * 4096 + l) * 256 + h * 32 + c0) =
                make_float4(ov[0], ov[1], ov[2], ov[3]);
        }

        CP_WAIT0();                            // Qr(pass+1) landed
        __syncthreads();                       // (5) epilogue done; Qr visible
    }
}

// ---------------------------------------------------------------------------
extern "C" void kernel_launch(void* const* d_in, const int* in_sizes, int n_in,
                              void* d_out, int out_size) {
    const float* qkv = (const float*)d_in[0];
    const float* cw  = (const float*)d_in[1];
    const float* cb  = (const float*)d_in[2];
    float* xout = (float*)d_out;
    float* attn = xout + (size_t)4 * 4096 * 256;    // x first, then attn

    const int SMEM = SMEM_FLOATS * 4;               // 210944 B
    cudaFuncSetAttribute(fused_attn_kernel,
                         cudaFuncAttributeMaxDynamicSharedMemorySize, SMEM);

    fused_attn_kernel<<<256, 512, SMEM>>>(qkv, cw, cb, attn, xout);
}

// round 14
// speedup vs baseline: 1.4360x; 1.4304x over previous
#include <cuda_runtime.h>
#include <cuda_bf16.h>
#include <cstdint>

#define SCALE 0.17677669529663687f

// ---- smem byte offsets ----
#define OFF_QH 0          // Qhi bf16 [128 rows][40]  (32 data + 8 pad)
#define OFF_QL 10240      // Qlo
#define OFF_KS 20480      // K stages: 2 x (Khi[64][40] 5120 + Klo 5120)
#define OFF_VT 40960      // V bf16 ch-major [32][520]  (33,280)
#define OFF_SR 74240      // 128 floats: 1/rowsum
#define OFF_W  74752      // conv w 288 f
#define OFF_CB 75904      // conv b 32 f
#define SMEM_BYTES 76032
#define OFF_VF 0          // fp32 V [32][516] aliases Q/K/VT in epilogue

#define L_OF(k) (((k) >> 3) * 64 + w2 * 8 + ((k) & 7))

#define MMA(d, a, b) asm volatile( \
  "mma.sync.aligned.m16n8k16.row.col.f32.bf16.bf16.f32 " \
  "{%0,%1,%2,%3}, {%4,%5,%6,%7}, {%8,%9}, {%0,%1,%2,%3};" \
  : "+f"((d)[0]), "+f"((d)[1]), "+f"((d)[2]), "+f"((d)[3]) \
  : "r"((a)[0]), "r"((a)[1]), "r"((a)[2]), "r"((a)[3]), "r"((b)[0]), "r"((b)[1]))

#define LDM4(r, addr) asm volatile( \
  "ldmatrix.sync.aligned.m8n8.x4.shared.b16 {%0,%1,%2,%3}, [%4];" \
  : "=r"((r)[0]), "=r"((r)[1]), "=r"((r)[2]), "=r"((r)[3]) : "r"(addr))

__device__ __forceinline__ uint32_t packpair(float a, float b, uint32_t& lo) {
    __nv_bfloat16 ah = __float2bfloat16(a), bh = __float2bfloat16(b);
    __nv_bfloat16 al = __float2bfloat16(a - __bfloat162float(ah));
    __nv_bfloat16 bl = __float2bfloat16(b - __bfloat162float(bh));
    lo = (uint32_t)__bfloat16_as_ushort(al) | ((uint32_t)__bfloat16_as_ushort(bl) << 16);
    return (uint32_t)__bfloat16_as_ushort(ah) | ((uint32_t)__bfloat16_as_ushort(bh) << 16);
}
__device__ __forceinline__ uint32_t packbf(float a, float b) {
    __nv_bfloat162 t = __floats2bfloat162_rn(a, b);
    return *reinterpret_cast<uint32_t*>(&t);
}

// ---------------------------------------------------------------------------
// CTA = (wh, qb): 128 q rows of window-head wh. 256 threads, 8 warps.
// Warp w owns q rows 16w..16w+15. 8 chunks of 64 keys:
//   S chunk = Q(hi/lo) K(hi/lo)^T via mma.m16n8k16 (hh+hl+lh)
//   exp in regs (no max-sub) -> unnormalized e: STG attn + accumulate rowsum
//   PV: e packed bf16 directly as A-frags (S D-frag == PV A-frag), V bf16 smem
// Epilogue: rowsum reduce -> attn in-place rescale (L2-hot) -> fp32 V reload
//   (aliased smem) -> O/sum + LePE conv -> STG x.
// ---------------------------------------------------------------------------
__global__ __launch_bounds__(256, 2)
void fused_attn_mma(const float* __restrict__ qkv, const float* __restrict__ cw,
                    const float* __restrict__ cb, float* __restrict__ attn_out,
                    float* __restrict__ xout) {
    extern __shared__ char smem[];
    uint32_t sb = (uint32_t)__cvta_generic_to_shared(smem);
    float* Sr  = (float*)(smem + OFF_SR);
    float* Wsh = (float*)(smem + OFF_W);
    float* CBs = (float*)(smem + OFF_CB);
    float* Vf  = (float*)(smem + OFF_VF);

    int bx = blockIdx.x, wh = bx >> 2, qb = bx & 3;
    int n = wh >> 3, h = wh & 7, b = n >> 3, w2 = n & 7;
    int tid = threadIdx.x, lane = tid & 31, warp = tid >> 5;
    int g = lane >> 2, t = lane & 3;

    const float* Qg = qkv + (size_t)(0 + b) * 4096 * 256;
    const float* Kg = qkv + (size_t)(4 + b) * 4096 * 256;
    const float* Vg = qkv + (size_t)(8 + b) * 4096 * 256;

    // ---- prologue: Q hi/lo (SCALE folded), V bf16, conv params ----
    {
        int row = tid >> 1, d0 = (tid & 1) * 16;
        int l = L_OF(qb * 128 + row);
        const float4* src = (const float4*)(Qg + (size_t)l * 256 + h * 32 + d0);
        uint32_t H[8], L[8];
        #pragma unroll
        for (int v4 = 0; v4 < 4; v4++) {
            float4 q = src[v4];
            q.x *= SCALE; q.y *= SCALE; q.z *= SCALE; q.w *= SCALE;
            H[2*v4]   = packpair(q.x, q.y, L[2*v4]);
            H[2*v4+1] = packpair(q.z, q.w, L[2*v4+1]);
        }
        char* qh = smem + OFF_QH + row * 80 + d0 * 2;
        char* ql = smem + OFF_QL + row * 80 + d0 * 2;
        *(uint4*)qh        = make_uint4(H[0], H[1], H[2], H[3]);
        *(uint4*)(qh + 16) = make_uint4(H[4], H[5], H[6], H[7]);
        *(uint4*)ql        = make_uint4(L[0], L[1], L[2], L[3]);
        *(uint4*)(ql + 16) = make_uint4(L[4], L[5], L[6], L[7]);
    }
    {   // V bf16 ch-major: warp covers 64 keys, lane = channel
        #pragma unroll 4
        for (int i = 0; i < 64; i += 2) {
            int k = warp * 64 + i;
            float v0 = Vg[(size_t)L_OF(k) * 256 + h * 32 + lane];
            float v1 = Vg[(size_t)L_OF(k + 1) * 256 + h * 32 + lane];
            *(uint32_t*)(smem + OFF_VT + lane * 1040 + k * 2) = packbf(v0, v1);
        }
    }
    for (int i = tid; i < 288; i += 256) Wsh[i] = cw[(h * 32) * 9 + i];
    if (tid < 32) CBs[tid] = cb[h * 32 + tid];

    // prefetch K chunk 0
    float4 pf0, pf1;
    {
        int krow = tid >> 2, d0 = (tid & 3) * 8;
        const float* p = Kg + (size_t)L_OF(krow) * 256 + h * 32 + d0;
        pf0 = *(const float4*)p; pf1 = *(const float4*)(p + 4);
    }
    __syncthreads();

    // Q A-frags (per warp, fixed)
    uint32_t aQh[2][4], aQl[2][4];
    {
        uint32_t laneQ = (uint32_t)((warp * 16 + (lane & 15)) * 80 + (lane >> 4) * 16);
        #pragma unroll
        for (int s = 0; s < 2; s++) {
            LDM4(aQh[s], sb + OFF_QH + s * 32 + laneQ);
            LDM4(aQl[s], sb + OFF_QL + s * 32 + laneQ);
        }
    }
    uint32_t laneK = (uint32_t)(((((lane >> 4) & 1) * 8) + (lane & 7)) * 80 + ((lane >> 3) & 1) * 16);
    uint32_t laneV = (uint32_t)(((((lane >> 4) & 1) * 8) + (lane & 7)) * 1040 + ((lane >> 3) & 1) * 16);

    float sumA = 0.f, sumB = 0.f;
    float oacc[4][4];
    #pragma unroll
    for (int i = 0; i < 4; i++)
        #pragma unroll
        for (int j = 0; j < 4; j++) oacc[i][j] = 0.f;

    float* attnp = attn_out + ((size_t)wh * 512 + qb * 128) * 512;

    for (int c = 0; c < 8; c++) {
        // stage prefetched K chunk (hi/lo split)
        uint32_t stg = OFF_KS + (uint32_t)(c & 1) * 10240u;
        {
            int krow = tid >> 2, d0b = (tid & 3) * 16;
            uint32_t H[4], L[4];
            H[0] = packpair(pf0.x, pf0.y, L[0]); H[1] = packpair(pf0.z, pf0.w, L[1]);
            H[2] = packpair(pf1.x, pf1.y, L[2]); H[3] = packpair(pf1.z, pf1.w, L[3]);
            *(uint4*)(smem + stg + krow * 80 + d0b)        = make_uint4(H[0], H[1], H[2], H[3]);
            *(uint4*)(smem + stg + 5120 + krow * 80 + d0b) = make_uint4(L[0], L[1], L[2], L[3]);
        }
        __syncthreads();
        if (c < 7) {
            int krow = tid >> 2, d0 = (tid & 3) * 8;
            const float* p = Kg + (size_t)L_OF((c + 1) * 64 + krow) * 256 + h * 32 + d0;
            pf0 = *(const float4*)p; pf1 = *(const float4*)(p + 4);
        }

        // ---- S chunk: 48 mmas ----
        float sacc[8][4];
        #pragma unroll
        for (int i = 0; i < 8; i++)
            #pragma unroll
            for (int j = 0; j < 4; j++) sacc[i][j] = 0.f;
        uint32_t kh = sb + stg;
        #pragma unroll
        for (int s = 0; s < 2; s++) {
            #pragma unroll
            for (int grp = 0; grp < 4; grp++) {
                int nt0 = grp * 2;
                uint32_t bh[4], bl[4];
                LDM4(bh, kh + (uint32_t)nt0 * 640 + s * 32 + laneK);
                LDM4(bl, kh + 5120 + (uint32_t)nt0 * 640 + s * 32 + laneK);
                MMA(sacc[nt0],     aQh[s], bh);
                MMA(sacc[nt0],     aQh[s], bl);
                MMA(sacc[nt0],     aQl[s], bh);
                MMA(sacc[nt0 + 1], aQh[s], bh + 2);
                MMA(sacc[nt0 + 1], aQh[s], bl + 2);
                MMA(sacc[nt0 + 1], aQl[s], bh + 2);
            }
        }

        // ---- exp (in place) + rowsums + unnormalized attn STG ----
        #pragma unroll
        for (int nt = 0; nt < 8; nt++) {
            float e0 = __expf(sacc[nt][0]), e1 = __expf(sacc[nt][1]);
            float e2 = __expf(sacc[nt][2]), e3 = __expf(sacc[nt][3]);
            sumA += e0 + e1; sumB += e2 + e3;
            sacc[nt][0] = e0; sacc[nt][1] = e1; sacc[nt][2] = e2; sacc[nt][3] = e3;
            float* p0 = attnp + (size_t)(warp * 16 + g) * 512 + c * 64 + nt * 8 + 2 * t;
            *(float2*)p0 = make_float2(e0, e1);
            *(float2*)(p0 + 8 * 512) = make_float2(e2, e3);
        }

        // ---- PV: S D-frags become A-frags; 16 mmas ----
        #pragma unroll
        for (int ks = 0; ks < 4; ks++) {
            uint32_t Ea[4] = {
                packbf(sacc[2*ks][0],   sacc[2*ks][1]),
                packbf(sacc[2*ks][2],   sacc[2*ks][3]),
                packbf(sacc[2*ks+1][0], sacc[2*ks+1][1]),
                packbf(sacc[2*ks+1][2], sacc[2*ks+1][3]) };
            uint32_t bv[4];
            LDM4(bv, sb + OFF_VT + (uint32_t)(c * 128 + ks * 32) + laneV);
            MMA(oacc[0], Ea, bv); MMA(oacc[1], Ea, bv + 2);
            LDM4(bv, sb + OFF_VT + 16640u + (uint32_t)(c * 128 + ks * 32) + laneV);
            MMA(oacc[2], Ea, bv); MMA(oacc[3], Ea, bv + 2);
        }
        __syncthreads();
    }

    // ---- rowsum reduce across the 4 lanes sharing a row ----
    sumA += __shfl_xor_sync(0xffffffffu, sumA, 1);
    sumA += __shfl_xor_sync(0xffffffffu, sumA, 2);
    sumB += __shfl_xor_sync(0xffffffffu, sumB, 1);
    sumB += __shfl_xor_sync(0xffffffffu, sumB, 2);
    float invA = 1.0f / sumA, invB = 1.0f / sumB;
    if (t == 0) { Sr[warp * 16 + g] = invA; Sr[warp * 16 + 8 + g] = invB; }
    __syncthreads();                 // Sr ready; all smem tiles now dead

    // ---- fp32 V reload into aliased smem (for exact LePE conv) ----
    #pragma unroll 4
    for (int i = 0; i < 64; i++) {
        int k = warp * 64 + i;
        Vf[lane * 516 + k] = Vg[(size_t)L_OF(k) * 256 + h * 32 + lane];
    }
    // ---- attn in-place rescale (L2-hot; block-coherent after sync) ----
    #pragma unroll 4
    for (int j = 0; j < 64; j++) {
        int idx = tid + j * 256;
        int row = idx >> 7, c4 = idx & 127;
        float inv = Sr[row];
        float* p = attnp + (size_t)row * 512 + c4 * 4;
        float4 v = *(float4*)p;
        v.x *= inv; v.y *= inv; v.z *= inv; v.w *= inv;
        *(float4*)p = v;
    }
    __syncthreads();                 // Vf ready

    // ---- epilogue: O/sum + LePE conv + STG x ----
    #pragma unroll
    for (int rsel = 0; rsel < 2; rsel++) {
        int R = warp * 16 + g + rsel * 8;
        int tg = qb * 128 + R;
        int hs = tg >> 3, ws = tg & 7;
        float inv = rsel ? invB : invA;
        int l = hs * 64 + w2 * 8 + ws;
        float* xp = xout + ((size_t)b * 4096 + l) * 256 + h * 32;
        #pragma unroll
        for (int ct = 0; ct < 4; ct++) {
            int ch0 = ct * 8 + 2 * t;
            float o0 = oacc[ct][2 * rsel]     * inv + CBs[ch0];
            float o1 = oacc[ct][2 * rsel + 1] * inv + CBs[ch0 + 1];
            #pragma unroll
            for (int dy = -1; dy <= 1; dy++) {
                if ((unsigned)(hs + dy) >= 64u) continue;
                #pragma unroll
                for (int dx = -1; dx <= 1; dx++) {
                    if ((unsigned)(ws + dx) >= 8u) continue;
                    int kk = tg + dy * 8 + dx, wi = (dy + 1) * 3 + (dx + 1);
                    o0 += Vf[ch0 * 516 + kk]       * Wsh[ch0 * 9 + wi];
                    o1 += Vf[(ch0 + 1) * 516 + kk] * Wsh[(ch0 + 1) * 9 + wi];
                }
            }
            *(float2*)(xp + ch0) = make_float2(o0, o1);
        }
    }
}

// ---------------------------------------------------------------------------
extern "C" void kernel_launch(void* const* d_in, const int* in_sizes, int n_in,
                              void* d_out, int out_size) {
    const float* qkv = (const float*)d_in[0];
    const float* cw  = (const float*)d_in[1];
    const float* cb  = (const float*)d_in[2];
    float* xout = (float*)d_out;
    float* attn = xout + (size_t)4 * 4096 * 256;    // x first, then attn

    cudaFuncSetAttribute(fused_attn_mma,
                         cudaFuncAttributeMaxDynamicSharedMemorySize, SMEM_BYTES);
    fused_attn_mma<<<1024, 256, SMEM_BYTES>>>(qkv, cw, cb, attn, xout);
}

// round 15
// speedup vs baseline: 1.5866x; 1.1049x over previous
#include <cuda_runtime.h>
#include <cuda_bf16.h>
#include <cstdint>

#define QSCALE 0.25503486f   // 32^-0.5 * log2(e): exp(s*SCALE) == exp2(s*QSCALE)

// ---- smem byte offsets ----
#define OFF_QH 0          // Qhi bf16 [128 rows][40]  (32 data + 8 pad)
#define OFF_QL 10240      // Qlo
#define OFF_KS 20480      // K stages: 2 x (Khi[64][40] 5120 + Klo 5120)
#define OFF_VT 40960      // V bf16 ch-major [32][520]  (33,280)
#define OFF_SR 74240      // 128 floats: 1/rowsum
#define OFF_W  74752      // conv w 288 f
#define OFF_CB 75904      // conv b 32 f
#define SMEM_BYTES 76032
#define OFF_VF 0          // fp32 V [32][516] aliases Q/K/VT in epilogue

#define L_OF(k) (((k) >> 3) * 64 + w2 * 8 + ((k) & 7))

#define MMA(d, a, b) asm volatile( \
  "mma.sync.aligned.m16n8k16.row.col.f32.bf16.bf16.f32 " \
  "{%0,%1,%2,%3}, {%4,%5,%6,%7}, {%8,%9}, {%0,%1,%2,%3};" \
  : "+f"((d)[0]), "+f"((d)[1]), "+f"((d)[2]), "+f"((d)[3]) \
  : "r"((a)[0]), "r"((a)[1]), "r"((a)[2]), "r"((a)[3]), "r"((b)[0]), "r"((b)[1]))

#define LDM4(r, addr) asm volatile( \
  "ldmatrix.sync.aligned.m8n8.x4.shared.b16 {%0,%1,%2,%3}, [%4];" \
  : "=r"((r)[0]), "=r"((r)[1]), "=r"((r)[2]), "=r"((r)[3]) : "r"(addr))

#define EX2(y, x) asm("ex2.approx.f32 %0, %1;" : "=f"(y) : "f"(x))

__device__ __forceinline__ uint32_t packpair(float a, float b, uint32_t& lo) {
    __nv_bfloat16 ah = __float2bfloat16(a), bh = __float2bfloat16(b);
    __nv_bfloat16 al = __float2bfloat16(a - __bfloat162float(ah));
    __nv_bfloat16 bl = __float2bfloat16(b - __bfloat162float(bh));
    lo = (uint32_t)__bfloat16_as_ushort(al) | ((uint32_t)__bfloat16_as_ushort(bl) << 16);
    return (uint32_t)__bfloat16_as_ushort(ah) | ((uint32_t)__bfloat16_as_ushort(bh) << 16);
}
__device__ __forceinline__ uint32_t packbf(float a, float b) {
    __nv_bfloat162 t = __floats2bfloat162_rn(a, b);
    return *reinterpret_cast<uint32_t*>(&t);
}

// ---------------------------------------------------------------------------
// CTA = (wh, qb): 128 q rows of window-head wh. 256 threads, 8 warps.
// Warp w owns q rows 16w..16w+15. 8 chunks of 64 keys:
//   S chunk = Q(hi/lo) K(hi/lo)^T via mma.m16n8k16 (hh+hl+lh, 2-way ILP)
//   exp2 in regs (QSCALE pre-folded, no max-sub) -> unnormalized e:
//   STG attn + rowsum accumulate; PV: e bf16 A-frags direct from S D-frags.
// Single sync per chunk (2-stage K ring makes the bottom sync redundant).
// Epilogue: rowsum reduce -> attn in-place rescale (L2-hot) -> fp32 V reload
//   (aliased smem) -> O/sum + LePE conv -> STG x.
// ---------------------------------------------------------------------------
__global__ __launch_bounds__(256, 2)
void fused_attn_mma(const float* __restrict__ qkv, const float* __restrict__ cw,
                    const float* __restrict__ cb, float* __restrict__ attn_out,
                    float* __restrict__ xout) {
    extern __shared__ char smem[];
    uint32_t sb = (uint32_t)__cvta_generic_to_shared(smem);
    float* Sr  = (float*)(smem + OFF_SR);
    float* Wsh = (float*)(smem + OFF_W);
    float* CBs = (float*)(smem + OFF_CB);
    float* Vf  = (float*)(smem + OFF_VF);

    int bx = blockIdx.x, wh = bx >> 2, qb = bx & 3;
    int n = wh >> 3, h = wh & 7, b = n >> 3, w2 = n & 7;
    int tid = threadIdx.x, lane = tid & 31, warp = tid >> 5;
    int g = lane >> 2, t = lane & 3;

    const float* Qg = qkv + (size_t)(0 + b) * 4096 * 256;
    const float* Kg = qkv + (size_t)(4 + b) * 4096 * 256;
    const float* Vg = qkv + (size_t)(8 + b) * 4096 * 256;

    // ---- prologue: Q hi/lo (QSCALE folded), V bf16, conv params ----
    {
        int row = tid >> 1, d0 = (tid & 1) * 16;
        int l = L_OF(qb * 128 + row);
        const float4* src = (const float4*)(Qg + (size_t)l * 256 + h * 32 + d0);
        uint32_t H[8], L[8];
        #pragma unroll
        for (int v4 = 0; v4 < 4; v4++) {
            float4 q = src[v4];
            q.x *= QSCALE; q.y *= QSCALE; q.z *= QSCALE; q.w *= QSCALE;
            H[2*v4]   = packpair(q.x, q.y, L[2*v4]);
            H[2*v4+1] = packpair(q.z, q.w, L[2*v4+1]);
        }
        char* qh = smem + OFF_QH + row * 80 + d0 * 2;
        char* ql = smem + OFF_QL + row * 80 + d0 * 2;
        *(uint4*)qh        = make_uint4(H[0], H[1], H[2], H[3]);
        *(uint4*)(qh + 16) = make_uint4(H[4], H[5], H[6], H[7]);
        *(uint4*)ql        = make_uint4(L[0], L[1], L[2], L[3]);
        *(uint4*)(ql + 16) = make_uint4(L[4], L[5], L[6], L[7]);
    }
    {   // V bf16 ch-major: warp covers 64 keys, lane = channel
        #pragma unroll 4
        for (int i = 0; i < 64; i += 2) {
            int k = warp * 64 + i;
            float v0 = Vg[(size_t)L_OF(k) * 256 + h * 32 + lane];
            float v1 = Vg[(size_t)L_OF(k + 1) * 256 + h * 32 + lane];
            *(uint32_t*)(smem + OFF_VT + lane * 1040 + k * 2) = packbf(v0, v1);
        }
    }
    for (int i = tid; i < 288; i += 256) Wsh[i] = cw[(h * 32) * 9 + i];
    if (tid < 32) CBs[tid] = cb[h * 32 + tid];

    // prefetch K chunk 0
    float4 pf0, pf1;
    {
        int krow = tid >> 2, d0 = (tid & 3) * 8;
        const float* p = Kg + (size_t)L_OF(krow) * 256 + h * 32 + d0;
        pf0 = *(const float4*)p; pf1 = *(const float4*)(p + 4);
    }
    __syncthreads();

    // Q A-frags (per warp, fixed)
    uint32_t aQh[2][4], aQl[2][4];
    {
        uint32_t laneQ = (uint32_t)((warp * 16 + (lane & 15)) * 80 + (lane >> 4) * 16);
        #pragma unroll
        for (int s = 0; s < 2; s++) {
            LDM4(aQh[s], sb + OFF_QH + s * 32 + laneQ);
            LDM4(aQl[s], sb + OFF_QL + s * 32 + laneQ);
        }
    }
    uint32_t laneK = (uint32_t)(((((lane >> 4) & 1) * 8) + (lane & 7)) * 80 + ((lane >> 3) & 1) * 16);
    uint32_t laneV = (uint32_t)(((((lane >> 4) & 1) * 8) + (lane & 7)) * 1040 + ((lane >> 3) & 1) * 16);

    float sumA = 0.f, sumB = 0.f;
    float oacc[4][4];
    #pragma unroll
    for (int i = 0; i < 4; i++)
        #pragma unroll
        for (int j = 0; j < 4; j++) oacc[i][j] = 0.f;

    float* attnp = attn_out + ((size_t)wh * 512 + qb * 128) * 512;

    for (int c = 0; c < 8; c++) {
        // stage prefetched K chunk (hi/lo split) — single sync per iteration
        uint32_t stg = OFF_KS + (uint32_t)(c & 1) * 10240u;
        {
            int krow = tid >> 2, d0b = (tid & 3) * 16;
            uint32_t H[4], L[4];
            H[0] = packpair(pf0.x, pf0.y, L[0]); H[1] = packpair(pf0.z, pf0.w, L[1]);
            H[2] = packpair(pf1.x, pf1.y, L[2]); H[3] = packpair(pf1.z, pf1.w, L[3]);
            *(uint4*)(smem + stg + krow * 80 + d0b)        = make_uint4(H[0], H[1], H[2], H[3]);
            *(uint4*)(smem + stg + 5120 + krow * 80 + d0b) = make_uint4(L[0], L[1], L[2], L[3]);
        }
        __syncthreads();
        if (c < 7) {
            int krow = tid >> 2, d0 = (tid & 3) * 8;
            const float* p = Kg + (size_t)L_OF((c + 1) * 64 + krow) * 256 + h * 32 + d0;
            pf0 = *(const float4*)p; pf1 = *(const float4*)(p + 4);
        }

        // ---- S chunk: 48 mmas, nt0/nt1 chains interleaved (2-way ILP) ----
        float sacc[8][4];
        #pragma unroll
        for (int i = 0; i < 8; i++)
            #pragma unroll
            for (int j = 0; j < 4; j++) sacc[i][j] = 0.f;
        uint32_t kh = sb + stg;
        #pragma unroll
        for (int s = 0; s < 2; s++) {
            #pragma unroll
            for (int grp = 0; grp < 4; grp++) {
                int nt0 = grp * 2;
                uint32_t bh[4], bl[4];
                LDM4(bh, kh + (uint32_t)nt0 * 640 + s * 32 + laneK);
                LDM4(bl, kh + 5120 + (uint32_t)nt0 * 640 + s * 32 + laneK);
                MMA(sacc[nt0],     aQh[s], bh);
                MMA(sacc[nt0 + 1], aQh[s], bh + 2);
                MMA(sacc[nt0],     aQh[s], bl);
                MMA(sacc[nt0 + 1], aQh[s], bl + 2);
                MMA(sacc[nt0],     aQl[s], bh);
                MMA(sacc[nt0 + 1], aQl[s], bh + 2);
            }
        }

        // ---- exp2 (in place) + rowsums + unnormalized attn STG ----
        #pragma unroll
        for (int nt = 0; nt < 8; nt++) {
            float e0, e1, e2, e3;
            EX2(e0, sacc[nt][0]); EX2(e1, sacc[nt][1]);
            EX2(e2, sacc[nt][2]); EX2(e3, sacc[nt][3]);
            sumA += e0 + e1; sumB += e2 + e3;
            sacc[nt][0] = e0; sacc[nt][1] = e1; sacc[nt][2] = e2; sacc[nt][3] = e3;
            float* p0 = attnp + (size_t)(warp * 16 + g) * 512 + c * 64 + nt * 8 + 2 * t;
            *(float2*)p0 = make_float2(e0, e1);
            *(float2*)(p0 + 8 * 512) = make_float2(e2, e3);
        }

        // ---- PV: S D-frags become A-frags; 16 mmas ----
        #pragma unroll
        for (int ks = 0; ks < 4; ks++) {
            uint32_t Ea[4] = {
                packbf(sacc[2*ks][0],   sacc[2*ks][1]),
                packbf(sacc[2*ks][2],   sacc[2*ks][3]),
                packbf(sacc[2*ks+1][0], sacc[2*ks+1][1]),
                packbf(sacc[2*ks+1][2], sacc[2*ks+1][3]) };
            uint32_t bv[4];
            LDM4(bv, sb + OFF_VT + (uint32_t)(c * 128 + ks * 32) + laneV);
            MMA(oacc[0], Ea, bv); MMA(oacc[1], Ea, bv + 2);
            LDM4(bv, sb + OFF_VT + 16640u + (uint32_t)(c * 128 + ks * 32) + laneV);
            MMA(oacc[2], Ea, bv); MMA(oacc[3], Ea, bv + 2);
        }
        // no bottom sync: 2-stage ring + top sync make it redundant
    }

    // ---- rowsum reduce across the 4 lanes sharing a row ----
    sumA += __shfl_xor_sync(0xffffffffu, sumA, 1);
    sumA += __shfl_xor_sync(0xffffffffu, sumA, 2);
    sumB += __shfl_xor_sync(0xffffffffu, sumB, 1);
    sumB += __shfl_xor_sync(0xffffffffu, sumB, 2);
    float invA = 1.0f / sumA, invB = 1.0f / sumB;
    if (t == 0) { Sr[warp * 16 + g] = invA; Sr[warp * 16 + 8 + g] = invB; }
    __syncthreads();                 // all compute done; Sr ready; smem dead

    // ---- fp32 V reload into aliased smem (for exact LePE conv) ----
    #pragma unroll 4
    for (int i = 0; i < 64; i++) {
        int k = warp * 64 + i;
        Vf[lane * 516 + k] = Vg[(size_t)L_OF(k) * 256 + h * 32 + lane];
    }
    // ---- attn in-place rescale (L2-hot; 2 lines/iter for MLP) ----
    #pragma unroll 4
    for (int j = 0; j < 32; j++) {
        int idx = tid + j * 512;
        int row0 = idx >> 7, c40 = idx & 127;
        int row1 = (idx + 256) >> 7, c41 = (idx + 256) & 127;
        float* p0 = attnp + (size_t)row0 * 512 + c40 * 4;
        float* p1 = attnp + (size_t)row1 * 512 + c41 * 4;
        float4 v0 = *(float4*)p0;
        float4 v1 = *(float4*)p1;
        float i0 = Sr[row0], i1 = Sr[row1];
        v0.x *= i0; v0.y *= i0; v0.z *= i0; v0.w *= i0;
        v1.x *= i1; v1.y *= i1; v1.z *= i1; v1.w *= i1;
        *(float4*)p0 = v0;
        *(float4*)p1 = v1;
    }
    __syncthreads();                 // Vf ready

    // ---- epilogue: O/sum + LePE conv + STG x ----
    #pragma unroll
    for (int rsel = 0; rsel < 2; rsel++) {
        int R = warp * 16 + g + rsel * 8;
        int tg = qb * 128 + R;
        int hs = tg >> 3, ws = tg & 7;
        float inv = rsel ? invB : invA;
        int l = hs * 64 + w2 * 8 + ws;
        float* xp = xout + ((size_t)b * 4096 + l) * 256 + h * 32;
        #pragma unroll
        for (int ct = 0; ct < 4; ct++) {
            int ch0 = ct * 8 + 2 * t;
            float o0 = oacc[ct][2 * rsel]     * inv + CBs[ch0];
            float o1 = oacc[ct][2 * rsel + 1] * inv + CBs[ch0 + 1];
            #pragma unroll
            for (int dy = -1; dy <= 1; dy++) {
                if ((unsigned)(hs + dy) >= 64u) continue;
                #pragma unroll
                for (int dx = -1; dx <= 1; dx++) {
                    if ((unsigned)(ws + dx) >= 8u) continue;
                    int kk = tg + dy * 8 + dx, wi = (dy + 1) * 3 + (dx + 1);
                    o0 += Vf[ch0 * 516 + kk]       * Wsh[ch0 * 9 + wi];
                    o1 += Vf[(ch0 + 1) * 516 + kk] * Wsh[(ch0 + 1) * 9 + wi];
                }
            }
            *(float2*)(xp + ch0) = make_float2(o0, o1);
        }
    }
}

// ---------------------------------------------------------------------------
extern "C" void kernel_launch(void* const* d_in, const int* in_sizes, int n_in,
                              void* d_out, int out_size) {
    const float* qkv = (const float*)d_in[0];
    const float* cw  = (const float*)d_in[1];
    const float* cb  = (const float*)d_in[2];
    float* xout = (float*)d_out;
    float* attn = xout + (size_t)4 * 4096 * 256;    // x first, then attn

    cudaFuncSetAttribute(fused_attn_mma,
                         cudaFuncAttributeMaxDynamicSharedMemorySize, SMEM_BYTES);
    fused_attn_mma<<<1024, 256, SMEM_BYTES>>>(qkv, cw, cb, attn, xout);
}